// round 11
// baseline (speedup 1.0000x reference)
#include <cuda_runtime.h>
#include <cuda_bf16.h>
#include <math.h>
#include <stdint.h>

#define B 8
#define N 256
#define L 16384
#define NMAT 16
#define SPLITS 8
#define KCH (L / SPLITS)   // 2048
#define EPSJ 2e-5f

// ---------------- scratch ----------------
__device__ float g_mean[NMAT][N];
__device__ float g_part[SPLITS][NMAT][N][N];
__device__ float g_A[NMAT][N * N];                // col-major lower
__device__ float g_LcT[B][N * N];
__device__ float g_M[B][N * N];
__device__ float g_v[B][N];
__device__ __nv_bfloat16 g_xhi[(size_t)NMAT * N * L];
__device__ __nv_bfloat16 g_xlo[(size_t)NMAT * N * L];
__device__ __nv_bfloat16 g_mhi[B * N * N];
__device__ __nv_bfloat16 g_mlo[B * N * N];

// ---------------- PTX helpers (baseline, no 'a' features) ----------------
__device__ __forceinline__ uint32_t smem_u32(const void* p) {
    uint32_t a;
    asm("{ .reg .u64 t; cvta.to.shared.u64 t, %1; cvt.u32.u64 %0, t; }" : "=r"(a) : "l"(p));
    return a;
}
__device__ __forceinline__ void cpa16(uint32_t s, const void* g) {
    asm volatile("cp.async.cg.shared.global [%0], [%1], 16;" :: "r"(s), "l"(g));
}
#define CP_COMMIT() asm volatile("cp.async.commit_group;" ::: "memory")
#define CP_WAIT1()  asm volatile("cp.async.wait_group 1;" ::: "memory")
#define CP_WAIT0()  asm volatile("cp.async.wait_group 0;" ::: "memory")

#define LDM_X4(r, addr) \
    asm volatile("ldmatrix.sync.aligned.m8n8.x4.shared.b16 {%0,%1,%2,%3}, [%4];" \
        : "=r"((r)[0]), "=r"((r)[1]), "=r"((r)[2]), "=r"((r)[3]) : "r"(addr))
#define LDM_X4T(r, addr) \
    asm volatile("ldmatrix.sync.aligned.m8n8.x4.trans.shared.b16 {%0,%1,%2,%3}, [%4];" \
        : "=r"((r)[0]), "=r"((r)[1]), "=r"((r)[2]), "=r"((r)[3]) : "r"(addr))

#define MMA(d, a, b0, b1) \
    asm volatile("mma.sync.aligned.m16n8k16.row.col.f32.bf16.bf16.f32 " \
        "{%0,%1,%2,%3}, {%4,%5,%6,%7}, {%8,%9}, {%0,%1,%2,%3};" \
        : "+f"((d)[0]), "+f"((d)[1]), "+f"((d)[2]), "+f"((d)[3]) \
        : "r"((a)[0]), "r"((a)[1]), "r"((a)[2]), "r"((a)[3]), "r"(b0), "r"(b1))

// ---------------- 1. convert fp32 -> (hi,lo) bf16 + row means ----------------
__global__ void k_convert(const float* __restrict__ xc, const float* __restrict__ xs) {
    int row = blockIdx.x;
    int mat = row >> 8;
    int n = row & 255;
    int b = mat >> 1;
    const float* x = ((mat & 1) ? xs : xc) + ((size_t)b * N + n) * L;
    __nv_bfloat16* hi = g_xhi + (size_t)row * L;
    __nv_bfloat16* lo = g_xlo + (size_t)row * L;
    int tid = threadIdx.x;
    float s = 0.f;
    for (int i = tid; i < L / 4; i += 256) {
        float4 v = ((const float4*)x)[i];
        s += v.x + v.y + v.z + v.w;
        __nv_bfloat16 h[4], l[4];
        float a[4] = {v.x, v.y, v.z, v.w};
#pragma unroll
        for (int j = 0; j < 4; j++) {
            h[j] = __float2bfloat16_rn(a[j]);
            l[j] = __float2bfloat16_rn(a[j] - __bfloat162float(h[j]));
        }
        ((uint2*)hi)[i] = *(uint2*)h;
        ((uint2*)lo)[i] = *(uint2*)l;
    }
    __shared__ float red[256];
    red[tid] = s;
    __syncthreads();
    for (int off = 128; off > 0; off >>= 1) {
        if (tid < off) red[tid] += red[tid + off];
        __syncthreads();
    }
    if (tid == 0) g_mean[mat][n] = red[0] * (1.f / (float)L);
}

// ---------------- 2. gram via mma.sync bf16x3 ----------------
#define GBK 64
#define GLDA 72                 // padded stride (elems): 144B, bank-rotating
#define GSTG (128 * GLDA)       // elems per 128x64 tile buffer
__global__ void __launch_bounds__(256, 1) k_gram_mma() {
    extern __shared__ __align__(16) __nv_bfloat16 sm[];
    int tid = threadIdx.x, lane = tid & 31, warp = tid >> 5;
    int m0 = (warp & 1) * 64;          // warp row: 2 x 64
    int n0w = (warp >> 1) * 32;        // warp col: 4 x 32
    int bid = blockIdx.x;
    int mat = bid / 24, rem = bid % 24, tile = rem >> 3, split = rem & 7;
    int tr = (tile == 0) ? 0 : 1;
    int tcc = (tile == 2) ? 1 : 0;
    bool diag = (tr == tcc);
    const __nv_bfloat16* Ahi = g_xhi + (size_t)(mat * N + tr * 128) * L;
    const __nv_bfloat16* Alo = g_xlo + (size_t)(mat * N + tr * 128) * L;
    const __nv_bfloat16* Bhi = g_xhi + (size_t)(mat * N + tcc * 128) * L;
    const __nv_bfloat16* Blo = g_xlo + (size_t)(mat * N + tcc * 128) * L;
    int k0 = split * KCH;

    uint32_t sb = smem_u32(sm);

    float acc[4][4][4];
#pragma unroll
    for (int i = 0; i < 4; i++)
#pragma unroll
        for (int j = 0; j < 4; j++)
#pragma unroll
            for (int q = 0; q < 4; q++) acc[i][j][q] = 0.f;

    // loader: stage st gets k-window kb
    auto load_stage = [&](int st, int kb) {
        uint32_t base = sb + (uint32_t)st * 4 * GSTG * 2;
#pragma unroll
        for (int q = 0; q < 4; q++) {
            int task = tid + q * 256;
            int row = task >> 3, seg = task & 7;
            uint32_t so = (uint32_t)(row * GLDA + seg * 8) * 2;
            size_t go = (size_t)row * L + kb + seg * 8;
            cpa16(base + so, Ahi + go);
            cpa16(base + GSTG * 2 + so, Alo + go);
            if (!diag) {
                cpa16(base + 2 * GSTG * 2 + so, Bhi + go);
                cpa16(base + 3 * GSTG * 2 + so, Blo + go);
            }
        }
        CP_COMMIT();
    };

    load_stage(0, k0);
    load_stage(1, k0 + GBK);

    const int NK = KCH / GBK;   // 32
    for (int kt = 0; kt < NK; kt++) {
        if (kt + 1 < NK) CP_WAIT1(); else CP_WAIT0();
        __syncthreads();
        uint32_t base = sb + (uint32_t)(kt & 1) * 4 * GSTG * 2;
        uint32_t a_hi = base, a_lo = base + GSTG * 2;
        uint32_t b_hi = diag ? a_hi : base + 2 * GSTG * 2;
        uint32_t b_lo = diag ? a_lo : base + 3 * GSTG * 2;

#pragma unroll
        for (int kk = 0; kk < GBK / 16; kk++) {
            uint32_t ah[4][4], al[4][4], bh[2][4], bl[2][4];
            int arow = m0 + (lane & 15);
            int acol = kk * 16 + (lane >> 4) * 8;
#pragma unroll
            for (int mi = 0; mi < 4; mi++) {
                uint32_t off = (uint32_t)((arow + mi * 16) * GLDA + acol) * 2;
                LDM_X4(ah[mi], a_hi + off);
                LDM_X4(al[mi], a_lo + off);
            }
            int brow = n0w + (lane >> 4) * 8 + (lane & 7);
            int bcol = kk * 16 + ((lane >> 3) & 1) * 8;
#pragma unroll
            for (int np = 0; np < 2; np++) {
                uint32_t off = (uint32_t)((brow + np * 16) * GLDA + bcol) * 2;
                LDM_X4(bh[np], b_hi + off);
                LDM_X4(bl[np], b_lo + off);
            }
#pragma unroll
            for (int mi = 0; mi < 4; mi++)
#pragma unroll
                for (int np = 0; np < 2; np++)
#pragma unroll
                    for (int h = 0; h < 2; h++) {
                        float* d = acc[mi][np * 2 + h];
                        MMA(d, ah[mi], bh[np][2 * h], bh[np][2 * h + 1]);
                        MMA(d, ah[mi], bl[np][2 * h], bl[np][2 * h + 1]);
                        MMA(d, al[mi], bh[np][2 * h], bh[np][2 * h + 1]);
                    }
        }
        __syncthreads();
        if (kt + 2 < NK) load_stage(kt & 1, k0 + (kt + 2) * GBK);
    }

    float* outp = &g_part[split][mat][0][0];
#pragma unroll
    for (int mi = 0; mi < 4; mi++)
#pragma unroll
        for (int nj = 0; nj < 4; nj++) {
            float* d = acc[mi][nj];
            int r0 = tr * 128 + m0 + mi * 16 + (lane >> 2);
            int c0 = tcc * 128 + n0w + nj * 8 + 2 * (lane & 3);
            *(float2*)&outp[(size_t)r0 * N + c0] = make_float2(d[0], d[1]);
            *(float2*)&outp[(size_t)(r0 + 8) * N + c0] = make_float2(d[2], d[3]);
        }
}

// ---------------- 3. reduce partials -> covariance (lower, col-major) ----------------
__global__ void k_reduce() {
    int bidx = blockIdx.x;
    int mat = bidx >> 8;
    int i = bidx & 255;
    int j = threadIdx.x;
    if (j <= i) {
        float s = 0.f;
#pragma unroll
        for (int sp = 0; sp < SPLITS; sp++) s += g_part[sp][mat][i][j];
        float mi = g_mean[mat][i];
        float mj = g_mean[mat][j];
        float cov = (s - (float)L * mi * mj) * (1.f / (float)(L - 1));
        if (i == j) cov += EPSJ;
        g_A[mat][j * N + i] = cov;
    }
}

// ---------------- 4. Cholesky ----------------
__global__ void k_chol() {
    float* A = g_A[blockIdx.x];
    int tid = threadIdx.x;
    __shared__ float colk[256];
    __shared__ float sdiag;
    for (int k = 0; k < N; k++) {
        if (tid == 0) sdiag = sqrtf(A[k * N + k]);
        __syncthreads();
        float d = sdiag;
        float l = 0.f;
        if (tid >= k) {
            l = A[k * N + tid] / d;
            A[k * N + tid] = l;
        }
        colk[tid] = l;
        __syncthreads();
        if (tid > k) {
#pragma unroll 4
            for (int i = k + 1; i <= tid; i++)
                A[i * N + tid] -= l * colk[i];
        }
        __syncthreads();
    }
}

// ---------------- 5. transpose Lc ----------------
__global__ void k_lct() {
    int b = blockIdx.x;
    const float* A = g_A[b * 2];
    float* T = g_LcT[b];
    for (int idx = threadIdx.x; idx < N * N; idx += 256) {
        int j = idx >> 8;
        int k = idx & 255;
        T[idx] = A[k * N + j];
    }
}

// ---------------- 6. solve M*Lc = Ls + v ----------------
#define RPAD 264
__global__ void k_solve() {
    int b = blockIdx.x >> 3;
    int i0 = (blockIdx.x & 7) << 5;
    int ms = b * 2 + 1;
    int tid = threadIdx.x;
    __shared__ float r[32][RPAD];
    __shared__ float rowj[256];
    __shared__ float mj[32];

    for (int idx = tid; idx < 32 * 256; idx += 256) {
        int j = idx >> 5;
        int ri = idx & 31;
        int i = i0 + ri;
        r[ri][j] = (i >= j) ? g_A[ms][j * N + i] : 0.f;
    }
    __syncthreads();

    int sub = tid & 7;
    int ri = tid >> 3;
    const float* LcT = g_LcT[b];
    float* Mrowbase = g_M[b];

    for (int j = N - 1; j >= 0; j--) {
        if (tid <= j) rowj[tid] = LcT[j * N + tid];
        __syncthreads();
        if (sub == 0) {
            float m = r[ri][j] / rowj[j];
            mj[ri] = m;
            r[ri][j] = m;
            Mrowbase[(i0 + ri) * N + j] = m;
        }
        __syncthreads();
        float m = mj[ri];
        for (int kk = sub; kk < j; kk += 8)
            r[ri][kk] -= m * rowj[kk];
        __syncthreads();
    }

    const float* cm = g_mean[b * 2];
    float s = 0.f;
    for (int kk = sub; kk < N; kk += 8) s += r[ri][kk] * cm[kk];
    s += __shfl_down_sync(0xffffffffu, s, 4);
    s += __shfl_down_sync(0xffffffffu, s, 2);
    s += __shfl_down_sync(0xffffffffu, s, 1);
    if (sub == 0) g_v[b][i0 + ri] = g_mean[ms][i0 + ri] - s;
}

// ---------------- 7. convert M -> hi/lo bf16 ----------------
__global__ void k_convM() {
    int idx = blockIdx.x * 256 + threadIdx.x;
    float4 v = ((const float4*)&g_M[0][0])[idx];
    __nv_bfloat16 h[4], l[4];
    float a[4] = {v.x, v.y, v.z, v.w};
#pragma unroll
    for (int j = 0; j < 4; j++) {
        h[j] = __float2bfloat16_rn(a[j]);
        l[j] = __float2bfloat16_rn(a[j] - __bfloat162float(h[j]));
    }
    ((uint2*)g_mhi)[idx] = *(uint2*)h;
    ((uint2*)g_mlo)[idx] = *(uint2*)l;
}

// ---------------- 8. color via mma.sync bf16x3: out = M@X + v ----------------
#define CBK 64
#define CLDM 72
#define CLDX 136
#define MSTG (128 * CLDM)   // 9216 elems
#define XSTG (64 * CLDX)    // 8704 elems
#define CSTG (2 * MSTG + 2 * XSTG)   // per-stage elems
__global__ void __launch_bounds__(256, 1) k_color_mma(float* __restrict__ out) {
    extern __shared__ __align__(16) __nv_bfloat16 sm[];
    int tid = threadIdx.x, lane = tid & 31, warp = tid >> 5;
    int m0 = (warp & 1) * 64;
    int n0w = (warp >> 1) * 32;
    int bid = blockIdx.x;
    int b = bid >> 8;
    int it = (bid >> 7) & 1;
    int lt = bid & 127;
    int i0 = it * 128;
    int l0 = lt * 128;
    const __nv_bfloat16* Mhi = g_mhi + (size_t)(b * N + i0) * 256;
    const __nv_bfloat16* Mlo = g_mlo + (size_t)(b * N + i0) * 256;
    const __nv_bfloat16* Xhi = g_xhi + (size_t)(b * 2) * N * L;
    const __nv_bfloat16* Xlo = g_xlo + (size_t)(b * 2) * N * L;

    uint32_t sb = smem_u32(sm);

    float acc[4][4][4];
#pragma unroll
    for (int i = 0; i < 4; i++)
#pragma unroll
        for (int j = 0; j < 4; j++)
#pragma unroll
            for (int q = 0; q < 4; q++) acc[i][j][q] = 0.f;

    auto load_stage = [&](int st, int kb) {
        uint32_t base = sb + (uint32_t)st * CSTG * 2;
#pragma unroll
        for (int q = 0; q < 4; q++) {
            int task = tid + q * 256;
            // M tile: 128 rows x 8 segs
            int mrow = task >> 3, mseg = task & 7;
            uint32_t mo = (uint32_t)(mrow * CLDM + mseg * 8) * 2;
            size_t mg = (size_t)mrow * 256 + kb + mseg * 8;
            cpa16(base + mo, Mhi + mg);
            cpa16(base + MSTG * 2 + mo, Mlo + mg);
            // X tile: 64 rows x 16 segs
            int xrow = task >> 4, xseg = task & 15;
            uint32_t xo = (uint32_t)(xrow * CLDX + xseg * 8) * 2;
            size_t xg = (size_t)(kb + xrow) * L + l0 + xseg * 8;
            cpa16(base + 2 * MSTG * 2 + xo, Xhi + xg);
            cpa16(base + 2 * MSTG * 2 + XSTG * 2 + xo, Xlo + xg);
        }
        CP_COMMIT();
    };

    load_stage(0, 0);
    load_stage(1, CBK);

    const int NK = N / CBK;   // 4
    for (int kt = 0; kt < NK; kt++) {
        if (kt + 1 < NK) CP_WAIT1(); else CP_WAIT0();
        __syncthreads();
        uint32_t base = sb + (uint32_t)(kt & 1) * CSTG * 2;
        uint32_t a_hi = base, a_lo = base + MSTG * 2;
        uint32_t x_hi = base + 2 * MSTG * 2, x_lo = x_hi + XSTG * 2;

#pragma unroll
        for (int kk = 0; kk < CBK / 16; kk++) {
            uint32_t ah[4][4], al[4][4], bh[2][4], bl[2][4];
            int arow = m0 + (lane & 15);
            int acol = kk * 16 + (lane >> 4) * 8;
#pragma unroll
            for (int mi = 0; mi < 4; mi++) {
                uint32_t off = (uint32_t)((arow + mi * 16) * CLDM + acol) * 2;
                LDM_X4(ah[mi], a_hi + off);
                LDM_X4(al[mi], a_lo + off);
            }
            int krow = kk * 16 + ((lane >> 3) & 1) * 8 + (lane & 7);
            int ncol = (lane >> 4) * 8;
#pragma unroll
            for (int np = 0; np < 2; np++) {
                uint32_t off = (uint32_t)(krow * CLDX + n0w + np * 16 + ncol) * 2;
                LDM_X4T(bh[np], x_hi + off);
                LDM_X4T(bl[np], x_lo + off);
            }
#pragma unroll
            for (int mi = 0; mi < 4; mi++)
#pragma unroll
                for (int np = 0; np < 2; np++)
#pragma unroll
                    for (int h = 0; h < 2; h++) {
                        float* d = acc[mi][np * 2 + h];
                        MMA(d, ah[mi], bh[np][2 * h], bh[np][2 * h + 1]);
                        MMA(d, ah[mi], bl[np][2 * h], bl[np][2 * h + 1]);
                        MMA(d, al[mi], bh[np][2 * h], bh[np][2 * h + 1]);
                    }
        }
        __syncthreads();
        if (kt + 2 < NK) load_stage(kt & 1, (kt + 2) * CBK);
    }

    float* O = out + (size_t)b * N * L;
#pragma unroll
    for (int mi = 0; mi < 4; mi++) {
        int r0 = i0 + m0 + mi * 16 + (lane >> 2);
        float v0 = g_v[b][r0];
        float v1 = g_v[b][r0 + 8];
#pragma unroll
        for (int nj = 0; nj < 4; nj++) {
            float* d = acc[mi][nj];
            int c0 = l0 + n0w + nj * 8 + 2 * (lane & 3);
            *(float2*)&O[(size_t)r0 * L + c0] = make_float2(d[0] + v0, d[1] + v0);
            *(float2*)&O[(size_t)(r0 + 8) * L + c0] = make_float2(d[2] + v1, d[3] + v1);
        }
    }
}

// ---------------- launch ----------------
extern "C" void kernel_launch(void* const* d_in, const int* in_sizes, int n_in,
                              void* d_out, int out_size) {
    const float* xc = (const float*)d_in[0];
    const float* xs = (const float*)d_in[1];
    float* out = (float*)d_out;

    static int inited = 0;
    (void)inited;
    cudaFuncSetAttribute(k_gram_mma, cudaFuncAttributeMaxDynamicSharedMemorySize,
                         2 * 4 * GSTG * 2);
    cudaFuncSetAttribute(k_color_mma, cudaFuncAttributeMaxDynamicSharedMemorySize,
                         2 * CSTG * 2);

    k_convert<<<NMAT * N, 256>>>(xc, xs);
    k_gram_mma<<<384, 256, 2 * 4 * GSTG * 2>>>();
    k_reduce<<<NMAT * N, 256>>>();
    k_chol<<<NMAT, 256>>>();
    k_lct<<<B, 256>>>();
    k_solve<<<B * 8, 256>>>();
    k_convM<<<512, 256>>>();
    k_color_mma<<<B * 2 * 128, 256, 2 * CSTG * 2>>>(out);
}

// round 12
// speedup vs baseline: 1.0062x; 1.0062x over previous
#include <cuda_runtime.h>
#include <cuda_bf16.h>
#include <math.h>
#include <stdint.h>

#define B 8
#define N 256
#define L 16384
#define NMAT 16
#define SPLITS 8
#define KCH (L / SPLITS)   // 2048
#define EPSJ 2e-5f

// ---------------- scratch ----------------
__device__ float g_mean[NMAT][N];
__device__ float g_part[SPLITS][NMAT][N][N];
__device__ float g_A[NMAT][N * N];                // col-major lower
__device__ float g_LcT[B][N * N];
__device__ float g_M[B][N * N];
__device__ float g_v[B][N];
__device__ __nv_bfloat16 g_xhi[(size_t)NMAT * N * L];
__device__ __nv_bfloat16 g_xlo[(size_t)NMAT * N * L];
__device__ __nv_bfloat16 g_mhi[B * N * N];
__device__ __nv_bfloat16 g_mlo[B * N * N];

// ---------------- PTX helpers (baseline, no 'a' features) ----------------
__device__ __forceinline__ uint32_t smem_u32(const void* p) {
    uint32_t a;
    asm("{ .reg .u64 t; cvta.to.shared.u64 t, %1; cvt.u32.u64 %0, t; }" : "=r"(a) : "l"(p));
    return a;
}
__device__ __forceinline__ void cpa16(uint32_t s, const void* g) {
    asm volatile("cp.async.cg.shared.global [%0], [%1], 16;" :: "r"(s), "l"(g));
}
#define CP_COMMIT() asm volatile("cp.async.commit_group;" ::: "memory")
#define CP_WAIT1()  asm volatile("cp.async.wait_group 1;" ::: "memory")
#define CP_WAIT0()  asm volatile("cp.async.wait_group 0;" ::: "memory")

#define LDM_X4(r, addr) \
    asm volatile("ldmatrix.sync.aligned.m8n8.x4.shared.b16 {%0,%1,%2,%3}, [%4];" \
        : "=r"((r)[0]), "=r"((r)[1]), "=r"((r)[2]), "=r"((r)[3]) : "r"(addr))
#define LDM_X4T(r, addr) \
    asm volatile("ldmatrix.sync.aligned.m8n8.x4.trans.shared.b16 {%0,%1,%2,%3}, [%4];" \
        : "=r"((r)[0]), "=r"((r)[1]), "=r"((r)[2]), "=r"((r)[3]) : "r"(addr))

#define MMA(d, a, b0, b1) \
    asm volatile("mma.sync.aligned.m16n8k16.row.col.f32.bf16.bf16.f32 " \
        "{%0,%1,%2,%3}, {%4,%5,%6,%7}, {%8,%9}, {%0,%1,%2,%3};" \
        : "+f"((d)[0]), "+f"((d)[1]), "+f"((d)[2]), "+f"((d)[3]) \
        : "r"((a)[0]), "r"((a)[1]), "r"((a)[2]), "r"((a)[3]), "r"(b0), "r"(b1))

// ---------------- 1. convert fp32 -> (hi,lo) bf16 + row means ----------------
__global__ void k_convert(const float* __restrict__ xc, const float* __restrict__ xs) {
    int row = blockIdx.x;
    int mat = row >> 8;
    int n = row & 255;
    int b = mat >> 1;
    const float* x = ((mat & 1) ? xs : xc) + ((size_t)b * N + n) * L;
    __nv_bfloat16* hi = g_xhi + (size_t)row * L;
    __nv_bfloat16* lo = g_xlo + (size_t)row * L;
    int tid = threadIdx.x;
    float s = 0.f;
    for (int i = tid; i < L / 4; i += 256) {
        float4 v = ((const float4*)x)[i];
        s += v.x + v.y + v.z + v.w;
        __nv_bfloat16 h[4], l[4];
        float a[4] = {v.x, v.y, v.z, v.w};
#pragma unroll
        for (int j = 0; j < 4; j++) {
            h[j] = __float2bfloat16_rn(a[j]);
            l[j] = __float2bfloat16_rn(a[j] - __bfloat162float(h[j]));
        }
        ((uint2*)hi)[i] = *(uint2*)h;
        ((uint2*)lo)[i] = *(uint2*)l;
    }
    __shared__ float red[256];
    red[tid] = s;
    __syncthreads();
    for (int off = 128; off > 0; off >>= 1) {
        if (tid < off) red[tid] += red[tid + off];
        __syncthreads();
    }
    if (tid == 0) g_mean[mat][n] = red[0] * (1.f / (float)L);
}

// ---------------- 2. gram via mma.sync bf16x3 ----------------
#define GBK 64
#define GLDA 72                 // padded stride (elems): 144B, bank-rotating
#define GSTG (128 * GLDA)       // elems per 128x64 tile buffer
__global__ void __launch_bounds__(256, 1) k_gram_mma() {
    extern __shared__ __align__(16) __nv_bfloat16 sm[];
    int tid = threadIdx.x, lane = tid & 31, warp = tid >> 5;
    int m0 = (warp & 1) * 64;          // warp row: 2 x 64
    int n0w = (warp >> 1) * 32;        // warp col: 4 x 32
    int bid = blockIdx.x;
    int mat = bid / 24, rem = bid % 24, tile = rem >> 3, split = rem & 7;
    int tr = (tile == 0) ? 0 : 1;
    int tcc = (tile == 2) ? 1 : 0;
    bool diag = (tr == tcc);
    const __nv_bfloat16* Ahi = g_xhi + (size_t)(mat * N + tr * 128) * L;
    const __nv_bfloat16* Alo = g_xlo + (size_t)(mat * N + tr * 128) * L;
    const __nv_bfloat16* Bhi = g_xhi + (size_t)(mat * N + tcc * 128) * L;
    const __nv_bfloat16* Blo = g_xlo + (size_t)(mat * N + tcc * 128) * L;
    int k0 = split * KCH;

    uint32_t sb = smem_u32(sm);

    float acc[4][4][4];
#pragma unroll
    for (int i = 0; i < 4; i++)
#pragma unroll
        for (int j = 0; j < 4; j++)
#pragma unroll
            for (int q = 0; q < 4; q++) acc[i][j][q] = 0.f;

    // loader: stage st gets k-window kb
    auto load_stage = [&](int st, int kb) {
        uint32_t base = sb + (uint32_t)st * 4 * GSTG * 2;
#pragma unroll
        for (int q = 0; q < 4; q++) {
            int task = tid + q * 256;
            int row = task >> 3, seg = task & 7;
            uint32_t so = (uint32_t)(row * GLDA + seg * 8) * 2;
            size_t go = (size_t)row * L + kb + seg * 8;
            cpa16(base + so, Ahi + go);
            cpa16(base + GSTG * 2 + so, Alo + go);
            if (!diag) {
                cpa16(base + 2 * GSTG * 2 + so, Bhi + go);
                cpa16(base + 3 * GSTG * 2 + so, Blo + go);
            }
        }
        CP_COMMIT();
    };

    load_stage(0, k0);
    load_stage(1, k0 + GBK);

    const int NK = KCH / GBK;   // 32
    for (int kt = 0; kt < NK; kt++) {
        if (kt + 1 < NK) CP_WAIT1(); else CP_WAIT0();
        __syncthreads();
        uint32_t base = sb + (uint32_t)(kt & 1) * 4 * GSTG * 2;
        uint32_t a_hi = base, a_lo = base + GSTG * 2;
        uint32_t b_hi = diag ? a_hi : base + 2 * GSTG * 2;
        uint32_t b_lo = diag ? a_lo : base + 3 * GSTG * 2;

#pragma unroll
        for (int kk = 0; kk < GBK / 16; kk++) {
            uint32_t ah[4][4], al[4][4], bh[2][4], bl[2][4];
            int arow = m0 + (lane & 15);
            int acol = kk * 16 + (lane >> 4) * 8;
#pragma unroll
            for (int mi = 0; mi < 4; mi++) {
                uint32_t off = (uint32_t)((arow + mi * 16) * GLDA + acol) * 2;
                LDM_X4(ah[mi], a_hi + off);
                LDM_X4(al[mi], a_lo + off);
            }
            int brow = n0w + (lane >> 4) * 8 + (lane & 7);
            int bcol = kk * 16 + ((lane >> 3) & 1) * 8;
#pragma unroll
            for (int np = 0; np < 2; np++) {
                uint32_t off = (uint32_t)((brow + np * 16) * GLDA + bcol) * 2;
                LDM_X4(bh[np], b_hi + off);
                LDM_X4(bl[np], b_lo + off);
            }
#pragma unroll
            for (int mi = 0; mi < 4; mi++)
#pragma unroll
                for (int np = 0; np < 2; np++)
#pragma unroll
                    for (int h = 0; h < 2; h++) {
                        float* d = acc[mi][np * 2 + h];
                        MMA(d, ah[mi], bh[np][2 * h], bh[np][2 * h + 1]);
                        MMA(d, ah[mi], bl[np][2 * h], bl[np][2 * h + 1]);
                        MMA(d, al[mi], bh[np][2 * h], bh[np][2 * h + 1]);
                    }
        }
        __syncthreads();
        if (kt + 2 < NK) load_stage(kt & 1, k0 + (kt + 2) * GBK);
    }

    float* outp = &g_part[split][mat][0][0];
#pragma unroll
    for (int mi = 0; mi < 4; mi++)
#pragma unroll
        for (int nj = 0; nj < 4; nj++) {
            float* d = acc[mi][nj];
            int r0 = tr * 128 + m0 + mi * 16 + (lane >> 2);
            int c0 = tcc * 128 + n0w + nj * 8 + 2 * (lane & 3);
            *(float2*)&outp[(size_t)r0 * N + c0] = make_float2(d[0], d[1]);
            *(float2*)&outp[(size_t)(r0 + 8) * N + c0] = make_float2(d[2], d[3]);
        }
}

// ---------------- 3. reduce partials -> covariance (lower, col-major) ----------------
__global__ void k_reduce() {
    int bidx = blockIdx.x;
    int mat = bidx >> 8;
    int i = bidx & 255;
    int j = threadIdx.x;
    if (j <= i) {
        float s = 0.f;
#pragma unroll
        for (int sp = 0; sp < SPLITS; sp++) s += g_part[sp][mat][i][j];
        float mi = g_mean[mat][i];
        float mj = g_mean[mat][j];
        float cov = (s - (float)L * mi * mj) * (1.f / (float)(L - 1));
        if (i == j) cov += EPSJ;
        g_A[mat][j * N + i] = cov;
    }
}

// ---------------- 4. Cholesky ----------------
__global__ void k_chol() {
    float* A = g_A[blockIdx.x];
    int tid = threadIdx.x;
    __shared__ float colk[256];
    __shared__ float sdiag;
    for (int k = 0; k < N; k++) {
        if (tid == 0) sdiag = sqrtf(A[k * N + k]);
        __syncthreads();
        float d = sdiag;
        float l = 0.f;
        if (tid >= k) {
            l = A[k * N + tid] / d;
            A[k * N + tid] = l;
        }
        colk[tid] = l;
        __syncthreads();
        if (tid > k) {
#pragma unroll 4
            for (int i = k + 1; i <= tid; i++)
                A[i * N + tid] -= l * colk[i];
        }
        __syncthreads();
    }
}

// ---------------- 5. transpose Lc ----------------
__global__ void k_lct() {
    int b = blockIdx.x;
    const float* A = g_A[b * 2];
    float* T = g_LcT[b];
    for (int idx = threadIdx.x; idx < N * N; idx += 256) {
        int j = idx >> 8;
        int k = idx & 255;
        T[idx] = A[k * N + j];
    }
}

// ---------------- 6. solve M*Lc = Ls + v ----------------
#define RPAD 264
__global__ void k_solve() {
    int b = blockIdx.x >> 3;
    int i0 = (blockIdx.x & 7) << 5;
    int ms = b * 2 + 1;
    int tid = threadIdx.x;
    __shared__ float r[32][RPAD];
    __shared__ float rowj[256];
    __shared__ float mj[32];

    for (int idx = tid; idx < 32 * 256; idx += 256) {
        int j = idx >> 5;
        int ri = idx & 31;
        int i = i0 + ri;
        r[ri][j] = (i >= j) ? g_A[ms][j * N + i] : 0.f;
    }
    __syncthreads();

    int sub = tid & 7;
    int ri = tid >> 3;
    const float* LcT = g_LcT[b];
    float* Mrowbase = g_M[b];

    for (int j = N - 1; j >= 0; j--) {
        if (tid <= j) rowj[tid] = LcT[j * N + tid];
        __syncthreads();
        if (sub == 0) {
            float m = r[ri][j] / rowj[j];
            mj[ri] = m;
            r[ri][j] = m;
            Mrowbase[(i0 + ri) * N + j] = m;
        }
        __syncthreads();
        float m = mj[ri];
        for (int kk = sub; kk < j; kk += 8)
            r[ri][kk] -= m * rowj[kk];
        __syncthreads();
    }

    const float* cm = g_mean[b * 2];
    float s = 0.f;
    for (int kk = sub; kk < N; kk += 8) s += r[ri][kk] * cm[kk];
    s += __shfl_down_sync(0xffffffffu, s, 4);
    s += __shfl_down_sync(0xffffffffu, s, 2);
    s += __shfl_down_sync(0xffffffffu, s, 1);
    if (sub == 0) g_v[b][i0 + ri] = g_mean[ms][i0 + ri] - s;
}

// ---------------- 7. convert M -> hi/lo bf16 ----------------
__global__ void k_convM() {
    int idx = blockIdx.x * 256 + threadIdx.x;
    float4 v = ((const float4*)&g_M[0][0])[idx];
    __nv_bfloat16 h[4], l[4];
    float a[4] = {v.x, v.y, v.z, v.w};
#pragma unroll
    for (int j = 0; j < 4; j++) {
        h[j] = __float2bfloat16_rn(a[j]);
        l[j] = __float2bfloat16_rn(a[j] - __bfloat162float(h[j]));
    }
    ((uint2*)g_mhi)[idx] = *(uint2*)h;
    ((uint2*)g_mlo)[idx] = *(uint2*)l;
}

// ---------------- 8. color via mma.sync bf16x3: out = M@X + v ----------------
#define CBK 64
#define CLDM 72
#define CLDX 136
#define MSTG (128 * CLDM)   // 9216 elems
#define XSTG (64 * CLDX)    // 8704 elems
#define CSTG (2 * MSTG + 2 * XSTG)   // per-stage elems
__global__ void __launch_bounds__(256, 1) k_color_mma(float* __restrict__ out) {
    extern __shared__ __align__(16) __nv_bfloat16 sm[];
    int tid = threadIdx.x, lane = tid & 31, warp = tid >> 5;
    int m0 = (warp & 1) * 64;
    int n0w = (warp >> 1) * 32;
    int bid = blockIdx.x;
    int b = bid >> 8;
    int it = (bid >> 7) & 1;
    int lt = bid & 127;
    int i0 = it * 128;
    int l0 = lt * 128;
    const __nv_bfloat16* Mhi = g_mhi + (size_t)(b * N + i0) * 256;
    const __nv_bfloat16* Mlo = g_mlo + (size_t)(b * N + i0) * 256;
    const __nv_bfloat16* Xhi = g_xhi + (size_t)(b * 2) * N * L;
    const __nv_bfloat16* Xlo = g_xlo + (size_t)(b * 2) * N * L;

    uint32_t sb = smem_u32(sm);

    float acc[4][4][4];
#pragma unroll
    for (int i = 0; i < 4; i++)
#pragma unroll
        for (int j = 0; j < 4; j++)
#pragma unroll
            for (int q = 0; q < 4; q++) acc[i][j][q] = 0.f;

    auto load_stage = [&](int st, int kb) {
        uint32_t base = sb + (uint32_t)st * CSTG * 2;
#pragma unroll
        for (int q = 0; q < 4; q++) {
            int task = tid + q * 256;
            // M tile: 128 rows x 8 segs
            int mrow = task >> 3, mseg = task & 7;
            uint32_t mo = (uint32_t)(mrow * CLDM + mseg * 8) * 2;
            size_t mg = (size_t)mrow * 256 + kb + mseg * 8;
            cpa16(base + mo, Mhi + mg);
            cpa16(base + MSTG * 2 + mo, Mlo + mg);
            // X tile: 64 rows x 16 segs
            int xrow = task >> 4, xseg = task & 15;
            uint32_t xo = (uint32_t)(xrow * CLDX + xseg * 8) * 2;
            size_t xg = (size_t)(kb + xrow) * L + l0 + xseg * 8;
            cpa16(base + 2 * MSTG * 2 + xo, Xhi + xg);
            cpa16(base + 2 * MSTG * 2 + XSTG * 2 + xo, Xlo + xg);
        }
        CP_COMMIT();
    };

    load_stage(0, 0);
    load_stage(1, CBK);

    const int NK = N / CBK;   // 4
    for (int kt = 0; kt < NK; kt++) {
        if (kt + 1 < NK) CP_WAIT1(); else CP_WAIT0();
        __syncthreads();
        uint32_t base = sb + (uint32_t)(kt & 1) * CSTG * 2;
        uint32_t a_hi = base, a_lo = base + MSTG * 2;
        uint32_t x_hi = base + 2 * MSTG * 2, x_lo = x_hi + XSTG * 2;

#pragma unroll
        for (int kk = 0; kk < CBK / 16; kk++) {
            uint32_t ah[4][4], al[4][4], bh[2][4], bl[2][4];
            int arow = m0 + (lane & 15);
            int acol = kk * 16 + (lane >> 4) * 8;
#pragma unroll
            for (int mi = 0; mi < 4; mi++) {
                uint32_t off = (uint32_t)((arow + mi * 16) * CLDM + acol) * 2;
                LDM_X4(ah[mi], a_hi + off);
                LDM_X4(al[mi], a_lo + off);
            }
            int krow = kk * 16 + ((lane >> 3) & 1) * 8 + (lane & 7);
            int ncol = (lane >> 4) * 8;
#pragma unroll
            for (int np = 0; np < 2; np++) {
                uint32_t off = (uint32_t)(krow * CLDX + n0w + np * 16 + ncol) * 2;
                LDM_X4T(bh[np], x_hi + off);
                LDM_X4T(bl[np], x_lo + off);
            }
#pragma unroll
            for (int mi = 0; mi < 4; mi++)
#pragma unroll
                for (int np = 0; np < 2; np++)
#pragma unroll
                    for (int h = 0; h < 2; h++) {
                        float* d = acc[mi][np * 2 + h];
                        MMA(d, ah[mi], bh[np][2 * h], bh[np][2 * h + 1]);
                        MMA(d, ah[mi], bl[np][2 * h], bl[np][2 * h + 1]);
                        MMA(d, al[mi], bh[np][2 * h], bh[np][2 * h + 1]);
                    }
        }
        __syncthreads();
        if (kt + 2 < NK) load_stage(kt & 1, (kt + 2) * CBK);
    }

    float* O = out + (size_t)b * N * L;
#pragma unroll
    for (int mi = 0; mi < 4; mi++) {
        int r0 = i0 + m0 + mi * 16 + (lane >> 2);
        float v0 = g_v[b][r0];
        float v1 = g_v[b][r0 + 8];
#pragma unroll
        for (int nj = 0; nj < 4; nj++) {
            float* d = acc[mi][nj];
            int c0 = l0 + n0w + nj * 8 + 2 * (lane & 3);
            *(float2*)&O[(size_t)r0 * L + c0] = make_float2(d[0] + v0, d[1] + v0);
            *(float2*)&O[(size_t)(r0 + 8) * L + c0] = make_float2(d[2] + v1, d[3] + v1);
        }
    }
}

// ---------------- launch ----------------
extern "C" void kernel_launch(void* const* d_in, const int* in_sizes, int n_in,
                              void* d_out, int out_size) {
    const float* xc = (const float*)d_in[0];
    const float* xs = (const float*)d_in[1];
    float* out = (float*)d_out;

    static int inited = 0;
    (void)inited;
    cudaFuncSetAttribute(k_gram_mma, cudaFuncAttributeMaxDynamicSharedMemorySize,
                         2 * 4 * GSTG * 2);
    cudaFuncSetAttribute(k_color_mma, cudaFuncAttributeMaxDynamicSharedMemorySize,
                         2 * CSTG * 2);

    k_convert<<<NMAT * N, 256>>>(xc, xs);
    k_gram_mma<<<384, 256, 2 * 4 * GSTG * 2>>>();
    k_reduce<<<NMAT * N, 256>>>();
    k_chol<<<NMAT, 256>>>();
    k_lct<<<B, 256>>>();
    k_solve<<<B * 8, 256>>>();
    k_convM<<<512, 256>>>();
    k_color_mma<<<B * 2 * 128, 256, 2 * CSTG * 2>>>(out);
}

// round 13
// speedup vs baseline: 1.0072x; 1.0010x over previous
#include <cuda_runtime.h>
#include <cuda_bf16.h>
#include <math.h>
#include <stdint.h>

#define B 8
#define N 256
#define L 16384
#define NMAT 16
#define SPLITS 8
#define KCH (L / SPLITS)   // 2048
#define EPSJ 2e-5f

// ---------------- scratch ----------------
__device__ float g_mean[NMAT][N];
__device__ float g_part[SPLITS][NMAT][N][N];
__device__ float g_A[NMAT][N * N];                // col-major lower
__device__ float g_LcT[B][N * N];
__device__ float g_M[B][N * N];
__device__ float g_v[B][N];
__device__ __nv_bfloat16 g_xhi[(size_t)NMAT * N * L];
__device__ __nv_bfloat16 g_xlo[(size_t)NMAT * N * L];
__device__ __nv_bfloat16 g_mhi[B * N * N];
__device__ __nv_bfloat16 g_mlo[B * N * N];

// ---------------- PTX helpers (baseline, no 'a' features) ----------------
__device__ __forceinline__ uint32_t smem_u32(const void* p) {
    uint32_t a;
    asm("{ .reg .u64 t; cvta.to.shared.u64 t, %1; cvt.u32.u64 %0, t; }" : "=r"(a) : "l"(p));
    return a;
}
__device__ __forceinline__ void cpa16(uint32_t s, const void* g) {
    asm volatile("cp.async.cg.shared.global [%0], [%1], 16;" :: "r"(s), "l"(g));
}
#define CP_COMMIT() asm volatile("cp.async.commit_group;" ::: "memory")
#define CP_WAIT1()  asm volatile("cp.async.wait_group 1;" ::: "memory")
#define CP_WAIT0()  asm volatile("cp.async.wait_group 0;" ::: "memory")

#define LDM_X4(r, addr) \
    asm volatile("ldmatrix.sync.aligned.m8n8.x4.shared.b16 {%0,%1,%2,%3}, [%4];" \
        : "=r"((r)[0]), "=r"((r)[1]), "=r"((r)[2]), "=r"((r)[3]) : "r"(addr))
#define LDM_X4T(r, addr) \
    asm volatile("ldmatrix.sync.aligned.m8n8.x4.trans.shared.b16 {%0,%1,%2,%3}, [%4];" \
        : "=r"((r)[0]), "=r"((r)[1]), "=r"((r)[2]), "=r"((r)[3]) : "r"(addr))

#define MMA(d, a, b0, b1) \
    asm volatile("mma.sync.aligned.m16n8k16.row.col.f32.bf16.bf16.f32 " \
        "{%0,%1,%2,%3}, {%4,%5,%6,%7}, {%8,%9}, {%0,%1,%2,%3};" \
        : "+f"((d)[0]), "+f"((d)[1]), "+f"((d)[2]), "+f"((d)[3]) \
        : "r"((a)[0]), "r"((a)[1]), "r"((a)[2]), "r"((a)[3]), "r"(b0), "r"(b1))

// ---------------- 1. convert fp32 -> (hi,lo) bf16 + row means ----------------
__global__ void k_convert(const float* __restrict__ xc, const float* __restrict__ xs) {
    int row = blockIdx.x;
    int mat = row >> 8;
    int n = row & 255;
    int b = mat >> 1;
    const float* x = ((mat & 1) ? xs : xc) + ((size_t)b * N + n) * L;
    __nv_bfloat16* hi = g_xhi + (size_t)row * L;
    __nv_bfloat16* lo = g_xlo + (size_t)row * L;
    int tid = threadIdx.x;
    float s = 0.f;
    for (int i = tid; i < L / 4; i += 256) {
        float4 v = ((const float4*)x)[i];
        s += v.x + v.y + v.z + v.w;
        __nv_bfloat16 h[4], l[4];
        float a[4] = {v.x, v.y, v.z, v.w};
#pragma unroll
        for (int j = 0; j < 4; j++) {
            h[j] = __float2bfloat16_rn(a[j]);
            l[j] = __float2bfloat16_rn(a[j] - __bfloat162float(h[j]));
        }
        ((uint2*)hi)[i] = *(uint2*)h;
        ((uint2*)lo)[i] = *(uint2*)l;
    }
    __shared__ float red[256];
    red[tid] = s;
    __syncthreads();
    for (int off = 128; off > 0; off >>= 1) {
        if (tid < off) red[tid] += red[tid + off];
        __syncthreads();
    }
    if (tid == 0) g_mean[mat][n] = red[0] * (1.f / (float)L);
}

// ---------------- 2. gram via mma.sync bf16x3 ----------------
#define GBK 64
#define GLDA 72                 // padded stride (elems): 144B, bank-rotating
#define GSTG (128 * GLDA)       // elems per 128x64 tile buffer
__global__ void __launch_bounds__(256, 1) k_gram_mma() {
    extern __shared__ __align__(16) __nv_bfloat16 sm[];
    int tid = threadIdx.x, lane = tid & 31, warp = tid >> 5;
    int m0 = (warp & 1) * 64;          // warp row: 2 x 64
    int n0w = (warp >> 1) * 32;        // warp col: 4 x 32
    int bid = blockIdx.x;
    int mat = bid / 24, rem = bid % 24, tile = rem >> 3, split = rem & 7;
    int tr = (tile == 0) ? 0 : 1;
    int tcc = (tile == 2) ? 1 : 0;
    bool diag = (tr == tcc);
    const __nv_bfloat16* Ahi = g_xhi + (size_t)(mat * N + tr * 128) * L;
    const __nv_bfloat16* Alo = g_xlo + (size_t)(mat * N + tr * 128) * L;
    const __nv_bfloat16* Bhi = g_xhi + (size_t)(mat * N + tcc * 128) * L;
    const __nv_bfloat16* Blo = g_xlo + (size_t)(mat * N + tcc * 128) * L;
    int k0 = split * KCH;

    uint32_t sb = smem_u32(sm);

    float acc[4][4][4];
#pragma unroll
    for (int i = 0; i < 4; i++)
#pragma unroll
        for (int j = 0; j < 4; j++)
#pragma unroll
            for (int q = 0; q < 4; q++) acc[i][j][q] = 0.f;

    // loader: stage st gets k-window kb
    auto load_stage = [&](int st, int kb) {
        uint32_t base = sb + (uint32_t)st * 4 * GSTG * 2;
#pragma unroll
        for (int q = 0; q < 4; q++) {
            int task = tid + q * 256;
            int row = task >> 3, seg = task & 7;
            uint32_t so = (uint32_t)(row * GLDA + seg * 8) * 2;
            size_t go = (size_t)row * L + kb + seg * 8;
            cpa16(base + so, Ahi + go);
            cpa16(base + GSTG * 2 + so, Alo + go);
            if (!diag) {
                cpa16(base + 2 * GSTG * 2 + so, Bhi + go);
                cpa16(base + 3 * GSTG * 2 + so, Blo + go);
            }
        }
        CP_COMMIT();
    };

    load_stage(0, k0);
    load_stage(1, k0 + GBK);

    const int NK = KCH / GBK;   // 32
    for (int kt = 0; kt < NK; kt++) {
        if (kt + 1 < NK) CP_WAIT1(); else CP_WAIT0();
        __syncthreads();
        uint32_t base = sb + (uint32_t)(kt & 1) * 4 * GSTG * 2;
        uint32_t a_hi = base, a_lo = base + GSTG * 2;
        uint32_t b_hi = diag ? a_hi : base + 2 * GSTG * 2;
        uint32_t b_lo = diag ? a_lo : base + 3 * GSTG * 2;

#pragma unroll
        for (int kk = 0; kk < GBK / 16; kk++) {
            uint32_t ah[4][4], al[4][4], bh[2][4], bl[2][4];
            int arow = m0 + (lane & 15);
            int acol = kk * 16 + (lane >> 4) * 8;
#pragma unroll
            for (int mi = 0; mi < 4; mi++) {
                uint32_t off = (uint32_t)((arow + mi * 16) * GLDA + acol) * 2;
                LDM_X4(ah[mi], a_hi + off);
                LDM_X4(al[mi], a_lo + off);
            }
            int brow = n0w + (lane >> 4) * 8 + (lane & 7);
            int bcol = kk * 16 + ((lane >> 3) & 1) * 8;
#pragma unroll
            for (int np = 0; np < 2; np++) {
                uint32_t off = (uint32_t)((brow + np * 16) * GLDA + bcol) * 2;
                LDM_X4(bh[np], b_hi + off);
                LDM_X4(bl[np], b_lo + off);
            }
#pragma unroll
            for (int mi = 0; mi < 4; mi++)
#pragma unroll
                for (int np = 0; np < 2; np++)
#pragma unroll
                    for (int h = 0; h < 2; h++) {
                        float* d = acc[mi][np * 2 + h];
                        MMA(d, ah[mi], bh[np][2 * h], bh[np][2 * h + 1]);
                        MMA(d, ah[mi], bl[np][2 * h], bl[np][2 * h + 1]);
                        MMA(d, al[mi], bh[np][2 * h], bh[np][2 * h + 1]);
                    }
        }
        __syncthreads();
        if (kt + 2 < NK) load_stage(kt & 1, k0 + (kt + 2) * GBK);
    }

    float* outp = &g_part[split][mat][0][0];
#pragma unroll
    for (int mi = 0; mi < 4; mi++)
#pragma unroll
        for (int nj = 0; nj < 4; nj++) {
            float* d = acc[mi][nj];
            int r0 = tr * 128 + m0 + mi * 16 + (lane >> 2);
            int c0 = tcc * 128 + n0w + nj * 8 + 2 * (lane & 3);
            *(float2*)&outp[(size_t)r0 * N + c0] = make_float2(d[0], d[1]);
            *(float2*)&outp[(size_t)(r0 + 8) * N + c0] = make_float2(d[2], d[3]);
        }
}

// ---------------- 3. reduce partials -> covariance (lower, col-major) ----------------
__global__ void k_reduce() {
    int bidx = blockIdx.x;
    int mat = bidx >> 8;
    int i = bidx & 255;
    int j = threadIdx.x;
    if (j <= i) {
        float s = 0.f;
#pragma unroll
        for (int sp = 0; sp < SPLITS; sp++) s += g_part[sp][mat][i][j];
        float mi = g_mean[mat][i];
        float mj = g_mean[mat][j];
        float cov = (s - (float)L * mi * mj) * (1.f / (float)(L - 1));
        if (i == j) cov += EPSJ;
        g_A[mat][j * N + i] = cov;
    }
}

// ---------------- 4. Cholesky ----------------
__global__ void k_chol() {
    float* A = g_A[blockIdx.x];
    int tid = threadIdx.x;
    __shared__ float colk[256];
    __shared__ float sdiag;
    for (int k = 0; k < N; k++) {
        if (tid == 0) sdiag = sqrtf(A[k * N + k]);
        __syncthreads();
        float d = sdiag;
        float l = 0.f;
        if (tid >= k) {
            l = A[k * N + tid] / d;
            A[k * N + tid] = l;
        }
        colk[tid] = l;
        __syncthreads();
        if (tid > k) {
#pragma unroll 4
            for (int i = k + 1; i <= tid; i++)
                A[i * N + tid] -= l * colk[i];
        }
        __syncthreads();
    }
}

// ---------------- 5. transpose Lc ----------------
__global__ void k_lct() {
    int b = blockIdx.x;
    const float* A = g_A[b * 2];
    float* T = g_LcT[b];
    for (int idx = threadIdx.x; idx < N * N; idx += 256) {
        int j = idx >> 8;
        int k = idx & 255;
        T[idx] = A[k * N + j];
    }
}

// ---------------- 6. solve M*Lc = Ls + v ----------------
#define RPAD 264
__global__ void k_solve() {
    int b = blockIdx.x >> 3;
    int i0 = (blockIdx.x & 7) << 5;
    int ms = b * 2 + 1;
    int tid = threadIdx.x;
    __shared__ float r[32][RPAD];
    __shared__ float rowj[256];
    __shared__ float mj[32];

    for (int idx = tid; idx < 32 * 256; idx += 256) {
        int j = idx >> 5;
        int ri = idx & 31;
        int i = i0 + ri;
        r[ri][j] = (i >= j) ? g_A[ms][j * N + i] : 0.f;
    }
    __syncthreads();

    int sub = tid & 7;
    int ri = tid >> 3;
    const float* LcT = g_LcT[b];
    float* Mrowbase = g_M[b];

    for (int j = N - 1; j >= 0; j--) {
        if (tid <= j) rowj[tid] = LcT[j * N + tid];
        __syncthreads();
        if (sub == 0) {
            float m = r[ri][j] / rowj[j];
            mj[ri] = m;
            r[ri][j] = m;
            Mrowbase[(i0 + ri) * N + j] = m;
        }
        __syncthreads();
        float m = mj[ri];
        for (int kk = sub; kk < j; kk += 8)
            r[ri][kk] -= m * rowj[kk];
        __syncthreads();
    }

    const float* cm = g_mean[b * 2];
    float s = 0.f;
    for (int kk = sub; kk < N; kk += 8) s += r[ri][kk] * cm[kk];
    s += __shfl_down_sync(0xffffffffu, s, 4);
    s += __shfl_down_sync(0xffffffffu, s, 2);
    s += __shfl_down_sync(0xffffffffu, s, 1);
    if (sub == 0) g_v[b][i0 + ri] = g_mean[ms][i0 + ri] - s;
}

// ---------------- 7. convert M -> hi/lo bf16 ----------------
__global__ void k_convM() {
    int idx = blockIdx.x * 256 + threadIdx.x;
    float4 v = ((const float4*)&g_M[0][0])[idx];
    __nv_bfloat16 h[4], l[4];
    float a[4] = {v.x, v.y, v.z, v.w};
#pragma unroll
    for (int j = 0; j < 4; j++) {
        h[j] = __float2bfloat16_rn(a[j]);
        l[j] = __float2bfloat16_rn(a[j] - __bfloat162float(h[j]));
    }
    ((uint2*)g_mhi)[idx] = *(uint2*)h;
    ((uint2*)g_mlo)[idx] = *(uint2*)l;
}

// ---------------- 8. color via mma.sync bf16x3: out = M@X + v ----------------
#define CBK 64
#define CLDM 72
#define CLDX 136
#define MSTG (128 * CLDM)   // 9216 elems
#define XSTG (64 * CLDX)    // 8704 elems
#define CSTG (2 * MSTG + 2 * XSTG)   // per-stage elems
__global__ void __launch_bounds__(256, 1) k_color_mma(float* __restrict__ out) {
    extern __shared__ __align__(16) __nv_bfloat16 sm[];
    int tid = threadIdx.x, lane = tid & 31, warp = tid >> 5;
    int m0 = (warp & 1) * 64;
    int n0w = (warp >> 1) * 32;
    int bid = blockIdx.x;
    int b = bid >> 8;
    int it = (bid >> 7) & 1;
    int lt = bid & 127;
    int i0 = it * 128;
    int l0 = lt * 128;
    const __nv_bfloat16* Mhi = g_mhi + (size_t)(b * N + i0) * 256;
    const __nv_bfloat16* Mlo = g_mlo + (size_t)(b * N + i0) * 256;
    const __nv_bfloat16* Xhi = g_xhi + (size_t)(b * 2) * N * L;
    const __nv_bfloat16* Xlo = g_xlo + (size_t)(b * 2) * N * L;

    uint32_t sb = smem_u32(sm);

    float acc[4][4][4];
#pragma unroll
    for (int i = 0; i < 4; i++)
#pragma unroll
        for (int j = 0; j < 4; j++)
#pragma unroll
            for (int q = 0; q < 4; q++) acc[i][j][q] = 0.f;

    auto load_stage = [&](int st, int kb) {
        uint32_t base = sb + (uint32_t)st * CSTG * 2;
#pragma unroll
        for (int q = 0; q < 4; q++) {
            int task = tid + q * 256;
            // M tile: 128 rows x 8 segs
            int mrow = task >> 3, mseg = task & 7;
            uint32_t mo = (uint32_t)(mrow * CLDM + mseg * 8) * 2;
            size_t mg = (size_t)mrow * 256 + kb + mseg * 8;
            cpa16(base + mo, Mhi + mg);
            cpa16(base + MSTG * 2 + mo, Mlo + mg);
            // X tile: 64 rows x 16 segs
            int xrow = task >> 4, xseg = task & 15;
            uint32_t xo = (uint32_t)(xrow * CLDX + xseg * 8) * 2;
            size_t xg = (size_t)(kb + xrow) * L + l0 + xseg * 8;
            cpa16(base + 2 * MSTG * 2 + xo, Xhi + xg);
            cpa16(base + 2 * MSTG * 2 + XSTG * 2 + xo, Xlo + xg);
        }
        CP_COMMIT();
    };

    load_stage(0, 0);
    load_stage(1, CBK);

    const int NK = N / CBK;   // 4
    for (int kt = 0; kt < NK; kt++) {
        if (kt + 1 < NK) CP_WAIT1(); else CP_WAIT0();
        __syncthreads();
        uint32_t base = sb + (uint32_t)(kt & 1) * CSTG * 2;
        uint32_t a_hi = base, a_lo = base + MSTG * 2;
        uint32_t x_hi = base + 2 * MSTG * 2, x_lo = x_hi + XSTG * 2;

#pragma unroll
        for (int kk = 0; kk < CBK / 16; kk++) {
            uint32_t ah[4][4], al[4][4], bh[2][4], bl[2][4];
            int arow = m0 + (lane & 15);
            int acol = kk * 16 + (lane >> 4) * 8;
#pragma unroll
            for (int mi = 0; mi < 4; mi++) {
                uint32_t off = (uint32_t)((arow + mi * 16) * CLDM + acol) * 2;
                LDM_X4(ah[mi], a_hi + off);
                LDM_X4(al[mi], a_lo + off);
            }
            int krow = kk * 16 + ((lane >> 3) & 1) * 8 + (lane & 7);
            int ncol = (lane >> 4) * 8;
#pragma unroll
            for (int np = 0; np < 2; np++) {
                uint32_t off = (uint32_t)(krow * CLDX + n0w + np * 16 + ncol) * 2;
                LDM_X4T(bh[np], x_hi + off);
                LDM_X4T(bl[np], x_lo + off);
            }
#pragma unroll
            for (int mi = 0; mi < 4; mi++)
#pragma unroll
                for (int np = 0; np < 2; np++)
#pragma unroll
                    for (int h = 0; h < 2; h++) {
                        float* d = acc[mi][np * 2 + h];
                        MMA(d, ah[mi], bh[np][2 * h], bh[np][2 * h + 1]);
                        MMA(d, ah[mi], bl[np][2 * h], bl[np][2 * h + 1]);
                        MMA(d, al[mi], bh[np][2 * h], bh[np][2 * h + 1]);
                    }
        }
        __syncthreads();
        if (kt + 2 < NK) load_stage(kt & 1, (kt + 2) * CBK);
    }

    float* O = out + (size_t)b * N * L;
#pragma unroll
    for (int mi = 0; mi < 4; mi++) {
        int r0 = i0 + m0 + mi * 16 + (lane >> 2);
        float v0 = g_v[b][r0];
        float v1 = g_v[b][r0 + 8];
#pragma unroll
        for (int nj = 0; nj < 4; nj++) {
            float* d = acc[mi][nj];
            int c0 = l0 + n0w + nj * 8 + 2 * (lane & 3);
            *(float2*)&O[(size_t)r0 * L + c0] = make_float2(d[0] + v0, d[1] + v0);
            *(float2*)&O[(size_t)(r0 + 8) * L + c0] = make_float2(d[2] + v1, d[3] + v1);
        }
    }
}

// ---------------- launch ----------------
extern "C" void kernel_launch(void* const* d_in, const int* in_sizes, int n_in,
                              void* d_out, int out_size) {
    const float* xc = (const float*)d_in[0];
    const float* xs = (const float*)d_in[1];
    float* out = (float*)d_out;

    static int inited = 0;
    (void)inited;
    cudaFuncSetAttribute(k_gram_mma, cudaFuncAttributeMaxDynamicSharedMemorySize,
                         2 * 4 * GSTG * 2);
    cudaFuncSetAttribute(k_color_mma, cudaFuncAttributeMaxDynamicSharedMemorySize,
                         2 * CSTG * 2);

    k_convert<<<NMAT * N, 256>>>(xc, xs);
    k_gram_mma<<<384, 256, 2 * 4 * GSTG * 2>>>();
    k_reduce<<<NMAT * N, 256>>>();
    k_chol<<<NMAT, 256>>>();
    k_lct<<<B, 256>>>();
    k_solve<<<B * 8, 256>>>();
    k_convM<<<512, 256>>>();
    k_color_mma<<<B * 2 * 128, 256, 2 * CSTG * 2>>>(out);
}

// round 14
// speedup vs baseline: 1.0074x; 1.0002x over previous
#include <cuda_runtime.h>
#include <cuda_bf16.h>
#include <math.h>
#include <stdint.h>

#define B 8
#define N 256
#define L 16384
#define NMAT 16
#define SPLITS 8
#define KCH (L / SPLITS)   // 2048
#define EPSJ 2e-5f

// ---------------- scratch ----------------
__device__ float g_mean[NMAT][N];
__device__ float g_part[SPLITS][NMAT][N][N];
__device__ float g_A[NMAT][N * N];                // col-major lower
__device__ float g_LcT[B][N * N];
__device__ float g_M[B][N * N];
__device__ float g_v[B][N];
__device__ __nv_bfloat16 g_xhi[(size_t)NMAT * N * L];
__device__ __nv_bfloat16 g_xlo[(size_t)NMAT * N * L];
__device__ __nv_bfloat16 g_mhi[B * N * N];
__device__ __nv_bfloat16 g_mlo[B * N * N];

// ---------------- PTX helpers (baseline, no 'a' features) ----------------
__device__ __forceinline__ uint32_t smem_u32(const void* p) {
    uint32_t a;
    asm("{ .reg .u64 t; cvta.to.shared.u64 t, %1; cvt.u32.u64 %0, t; }" : "=r"(a) : "l"(p));
    return a;
}
__device__ __forceinline__ void cpa16(uint32_t s, const void* g) {
    asm volatile("cp.async.cg.shared.global [%0], [%1], 16;" :: "r"(s), "l"(g));
}
#define CP_COMMIT() asm volatile("cp.async.commit_group;" ::: "memory")
#define CP_WAIT1()  asm volatile("cp.async.wait_group 1;" ::: "memory")
#define CP_WAIT0()  asm volatile("cp.async.wait_group 0;" ::: "memory")

#define LDM_X4(r, addr) \
    asm volatile("ldmatrix.sync.aligned.m8n8.x4.shared.b16 {%0,%1,%2,%3}, [%4];" \
        : "=r"((r)[0]), "=r"((r)[1]), "=r"((r)[2]), "=r"((r)[3]) : "r"(addr))
#define LDM_X4T(r, addr) \
    asm volatile("ldmatrix.sync.aligned.m8n8.x4.trans.shared.b16 {%0,%1,%2,%3}, [%4];" \
        : "=r"((r)[0]), "=r"((r)[1]), "=r"((r)[2]), "=r"((r)[3]) : "r"(addr))

#define MMA(d, a, b0, b1) \
    asm volatile("mma.sync.aligned.m16n8k16.row.col.f32.bf16.bf16.f32 " \
        "{%0,%1,%2,%3}, {%4,%5,%6,%7}, {%8,%9}, {%0,%1,%2,%3};" \
        : "+f"((d)[0]), "+f"((d)[1]), "+f"((d)[2]), "+f"((d)[3]) \
        : "r"((a)[0]), "r"((a)[1]), "r"((a)[2]), "r"((a)[3]), "r"(b0), "r"(b1))

// ---------------- 1. convert fp32 -> (hi,lo) bf16 + row means ----------------
__global__ void k_convert(const float* __restrict__ xc, const float* __restrict__ xs) {
    int row = blockIdx.x;
    int mat = row >> 8;
    int n = row & 255;
    int b = mat >> 1;
    const float* x = ((mat & 1) ? xs : xc) + ((size_t)b * N + n) * L;
    __nv_bfloat16* hi = g_xhi + (size_t)row * L;
    __nv_bfloat16* lo = g_xlo + (size_t)row * L;
    int tid = threadIdx.x;
    float s = 0.f;
    for (int i = tid; i < L / 4; i += 256) {
        float4 v = ((const float4*)x)[i];
        s += v.x + v.y + v.z + v.w;
        __nv_bfloat16 h[4], l[4];
        float a[4] = {v.x, v.y, v.z, v.w};
#pragma unroll
        for (int j = 0; j < 4; j++) {
            h[j] = __float2bfloat16_rn(a[j]);
            l[j] = __float2bfloat16_rn(a[j] - __bfloat162float(h[j]));
        }
        ((uint2*)hi)[i] = *(uint2*)h;
        ((uint2*)lo)[i] = *(uint2*)l;
    }
    __shared__ float red[256];
    red[tid] = s;
    __syncthreads();
    for (int off = 128; off > 0; off >>= 1) {
        if (tid < off) red[tid] += red[tid + off];
        __syncthreads();
    }
    if (tid == 0) g_mean[mat][n] = red[0] * (1.f / (float)L);
}

// ---------------- 2. gram via mma.sync bf16x3 ----------------
#define GBK 64
#define GLDA 72                 // padded stride (elems): 144B, bank-rotating
#define GSTG (128 * GLDA)       // elems per 128x64 tile buffer
__global__ void __launch_bounds__(256, 1) k_gram_mma() {
    extern __shared__ __align__(16) __nv_bfloat16 sm[];
    int tid = threadIdx.x, lane = tid & 31, warp = tid >> 5;
    int m0 = (warp & 1) * 64;          // warp row: 2 x 64
    int n0w = (warp >> 1) * 32;        // warp col: 4 x 32
    int bid = blockIdx.x;
    int mat = bid / 24, rem = bid % 24, tile = rem >> 3, split = rem & 7;
    int tr = (tile == 0) ? 0 : 1;
    int tcc = (tile == 2) ? 1 : 0;
    bool diag = (tr == tcc);
    const __nv_bfloat16* Ahi = g_xhi + (size_t)(mat * N + tr * 128) * L;
    const __nv_bfloat16* Alo = g_xlo + (size_t)(mat * N + tr * 128) * L;
    const __nv_bfloat16* Bhi = g_xhi + (size_t)(mat * N + tcc * 128) * L;
    const __nv_bfloat16* Blo = g_xlo + (size_t)(mat * N + tcc * 128) * L;
    int k0 = split * KCH;

    uint32_t sb = smem_u32(sm);

    float acc[4][4][4];
#pragma unroll
    for (int i = 0; i < 4; i++)
#pragma unroll
        for (int j = 0; j < 4; j++)
#pragma unroll
            for (int q = 0; q < 4; q++) acc[i][j][q] = 0.f;

    // loader: stage st gets k-window kb
    auto load_stage = [&](int st, int kb) {
        uint32_t base = sb + (uint32_t)st * 4 * GSTG * 2;
#pragma unroll
        for (int q = 0; q < 4; q++) {
            int task = tid + q * 256;
            int row = task >> 3, seg = task & 7;
            uint32_t so = (uint32_t)(row * GLDA + seg * 8) * 2;
            size_t go = (size_t)row * L + kb + seg * 8;
            cpa16(base + so, Ahi + go);
            cpa16(base + GSTG * 2 + so, Alo + go);
            if (!diag) {
                cpa16(base + 2 * GSTG * 2 + so, Bhi + go);
                cpa16(base + 3 * GSTG * 2 + so, Blo + go);
            }
        }
        CP_COMMIT();
    };

    load_stage(0, k0);
    load_stage(1, k0 + GBK);

    const int NK = KCH / GBK;   // 32
    for (int kt = 0; kt < NK; kt++) {
        if (kt + 1 < NK) CP_WAIT1(); else CP_WAIT0();
        __syncthreads();
        uint32_t base = sb + (uint32_t)(kt & 1) * 4 * GSTG * 2;
        uint32_t a_hi = base, a_lo = base + GSTG * 2;
        uint32_t b_hi = diag ? a_hi : base + 2 * GSTG * 2;
        uint32_t b_lo = diag ? a_lo : base + 3 * GSTG * 2;

#pragma unroll
        for (int kk = 0; kk < GBK / 16; kk++) {
            uint32_t ah[4][4], al[4][4], bh[2][4], bl[2][4];
            int arow = m0 + (lane & 15);
            int acol = kk * 16 + (lane >> 4) * 8;
#pragma unroll
            for (int mi = 0; mi < 4; mi++) {
                uint32_t off = (uint32_t)((arow + mi * 16) * GLDA + acol) * 2;
                LDM_X4(ah[mi], a_hi + off);
                LDM_X4(al[mi], a_lo + off);
            }
            int brow = n0w + (lane >> 4) * 8 + (lane & 7);
            int bcol = kk * 16 + ((lane >> 3) & 1) * 8;
#pragma unroll
            for (int np = 0; np < 2; np++) {
                uint32_t off = (uint32_t)((brow + np * 16) * GLDA + bcol) * 2;
                LDM_X4(bh[np], b_hi + off);
                LDM_X4(bl[np], b_lo + off);
            }
#pragma unroll
            for (int mi = 0; mi < 4; mi++)
#pragma unroll
                for (int np = 0; np < 2; np++)
#pragma unroll
                    for (int h = 0; h < 2; h++) {
                        float* d = acc[mi][np * 2 + h];
                        MMA(d, ah[mi], bh[np][2 * h], bh[np][2 * h + 1]);
                        MMA(d, ah[mi], bl[np][2 * h], bl[np][2 * h + 1]);
                        MMA(d, al[mi], bh[np][2 * h], bh[np][2 * h + 1]);
                    }
        }
        __syncthreads();
        if (kt + 2 < NK) load_stage(kt & 1, k0 + (kt + 2) * GBK);
    }

    float* outp = &g_part[split][mat][0][0];
#pragma unroll
    for (int mi = 0; mi < 4; mi++)
#pragma unroll
        for (int nj = 0; nj < 4; nj++) {
            float* d = acc[mi][nj];
            int r0 = tr * 128 + m0 + mi * 16 + (lane >> 2);
            int c0 = tcc * 128 + n0w + nj * 8 + 2 * (lane & 3);
            *(float2*)&outp[(size_t)r0 * N + c0] = make_float2(d[0], d[1]);
            *(float2*)&outp[(size_t)(r0 + 8) * N + c0] = make_float2(d[2], d[3]);
        }
}

// ---------------- 3. reduce partials -> covariance (lower, col-major) ----------------
__global__ void k_reduce() {
    int bidx = blockIdx.x;
    int mat = bidx >> 8;
    int i = bidx & 255;
    int j = threadIdx.x;
    if (j <= i) {
        float s = 0.f;
#pragma unroll
        for (int sp = 0; sp < SPLITS; sp++) s += g_part[sp][mat][i][j];
        float mi = g_mean[mat][i];
        float mj = g_mean[mat][j];
        float cov = (s - (float)L * mi * mj) * (1.f / (float)(L - 1));
        if (i == j) cov += EPSJ;
        g_A[mat][j * N + i] = cov;
    }
}

// ---------------- 4. Cholesky ----------------
__global__ void k_chol() {
    float* A = g_A[blockIdx.x];
    int tid = threadIdx.x;
    __shared__ float colk[256];
    __shared__ float sdiag;
    for (int k = 0; k < N; k++) {
        if (tid == 0) sdiag = sqrtf(A[k * N + k]);
        __syncthreads();
        float d = sdiag;
        float l = 0.f;
        if (tid >= k) {
            l = A[k * N + tid] / d;
            A[k * N + tid] = l;
        }
        colk[tid] = l;
        __syncthreads();
        if (tid > k) {
#pragma unroll 4
            for (int i = k + 1; i <= tid; i++)
                A[i * N + tid] -= l * colk[i];
        }
        __syncthreads();
    }
}

// ---------------- 5. transpose Lc ----------------
__global__ void k_lct() {
    int b = blockIdx.x;
    const float* A = g_A[b * 2];
    float* T = g_LcT[b];
    for (int idx = threadIdx.x; idx < N * N; idx += 256) {
        int j = idx >> 8;
        int k = idx & 255;
        T[idx] = A[k * N + j];
    }
}

// ---------------- 6. solve M*Lc = Ls + v ----------------
#define RPAD 264
__global__ void k_solve() {
    int b = blockIdx.x >> 3;
    int i0 = (blockIdx.x & 7) << 5;
    int ms = b * 2 + 1;
    int tid = threadIdx.x;
    __shared__ float r[32][RPAD];
    __shared__ float rowj[256];
    __shared__ float mj[32];

    for (int idx = tid; idx < 32 * 256; idx += 256) {
        int j = idx >> 5;
        int ri = idx & 31;
        int i = i0 + ri;
        r[ri][j] = (i >= j) ? g_A[ms][j * N + i] : 0.f;
    }
    __syncthreads();

    int sub = tid & 7;
    int ri = tid >> 3;
    const float* LcT = g_LcT[b];
    float* Mrowbase = g_M[b];

    for (int j = N - 1; j >= 0; j--) {
        if (tid <= j) rowj[tid] = LcT[j * N + tid];
        __syncthreads();
        if (sub == 0) {
            float m = r[ri][j] / rowj[j];
            mj[ri] = m;
            r[ri][j] = m;
            Mrowbase[(i0 + ri) * N + j] = m;
        }
        __syncthreads();
        float m = mj[ri];
        for (int kk = sub; kk < j; kk += 8)
            r[ri][kk] -= m * rowj[kk];
        __syncthreads();
    }

    const float* cm = g_mean[b * 2];
    float s = 0.f;
    for (int kk = sub; kk < N; kk += 8) s += r[ri][kk] * cm[kk];
    s += __shfl_down_sync(0xffffffffu, s, 4);
    s += __shfl_down_sync(0xffffffffu, s, 2);
    s += __shfl_down_sync(0xffffffffu, s, 1);
    if (sub == 0) g_v[b][i0 + ri] = g_mean[ms][i0 + ri] - s;
}

// ---------------- 7. convert M -> hi/lo bf16 ----------------
__global__ void k_convM() {
    int idx = blockIdx.x * 256 + threadIdx.x;
    float4 v = ((const float4*)&g_M[0][0])[idx];
    __nv_bfloat16 h[4], l[4];
    float a[4] = {v.x, v.y, v.z, v.w};
#pragma unroll
    for (int j = 0; j < 4; j++) {
        h[j] = __float2bfloat16_rn(a[j]);
        l[j] = __float2bfloat16_rn(a[j] - __bfloat162float(h[j]));
    }
    ((uint2*)g_mhi)[idx] = *(uint2*)h;
    ((uint2*)g_mlo)[idx] = *(uint2*)l;
}

// ---------------- 8. color via mma.sync bf16x3: out = M@X + v ----------------
#define CBK 64
#define CLDM 72
#define CLDX 136
#define MSTG (128 * CLDM)   // 9216 elems
#define XSTG (64 * CLDX)    // 8704 elems
#define CSTG (2 * MSTG + 2 * XSTG)   // per-stage elems
__global__ void __launch_bounds__(256, 1) k_color_mma(float* __restrict__ out) {
    extern __shared__ __align__(16) __nv_bfloat16 sm[];
    int tid = threadIdx.x, lane = tid & 31, warp = tid >> 5;
    int m0 = (warp & 1) * 64;
    int n0w = (warp >> 1) * 32;
    int bid = blockIdx.x;
    int b = bid >> 8;
    int it = (bid >> 7) & 1;
    int lt = bid & 127;
    int i0 = it * 128;
    int l0 = lt * 128;
    const __nv_bfloat16* Mhi = g_mhi + (size_t)(b * N + i0) * 256;
    const __nv_bfloat16* Mlo = g_mlo + (size_t)(b * N + i0) * 256;
    const __nv_bfloat16* Xhi = g_xhi + (size_t)(b * 2) * N * L;
    const __nv_bfloat16* Xlo = g_xlo + (size_t)(b * 2) * N * L;

    uint32_t sb = smem_u32(sm);

    float acc[4][4][4];
#pragma unroll
    for (int i = 0; i < 4; i++)
#pragma unroll
        for (int j = 0; j < 4; j++)
#pragma unroll
            for (int q = 0; q < 4; q++) acc[i][j][q] = 0.f;

    auto load_stage = [&](int st, int kb) {
        uint32_t base = sb + (uint32_t)st * CSTG * 2;
#pragma unroll
        for (int q = 0; q < 4; q++) {
            int task = tid + q * 256;
            // M tile: 128 rows x 8 segs
            int mrow = task >> 3, mseg = task & 7;
            uint32_t mo = (uint32_t)(mrow * CLDM + mseg * 8) * 2;
            size_t mg = (size_t)mrow * 256 + kb + mseg * 8;
            cpa16(base + mo, Mhi + mg);
            cpa16(base + MSTG * 2 + mo, Mlo + mg);
            // X tile: 64 rows x 16 segs
            int xrow = task >> 4, xseg = task & 15;
            uint32_t xo = (uint32_t)(xrow * CLDX + xseg * 8) * 2;
            size_t xg = (size_t)(kb + xrow) * L + l0 + xseg * 8;
            cpa16(base + 2 * MSTG * 2 + xo, Xhi + xg);
            cpa16(base + 2 * MSTG * 2 + XSTG * 2 + xo, Xlo + xg);
        }
        CP_COMMIT();
    };

    load_stage(0, 0);
    load_stage(1, CBK);

    const int NK = N / CBK;   // 4
    for (int kt = 0; kt < NK; kt++) {
        if (kt + 1 < NK) CP_WAIT1(); else CP_WAIT0();
        __syncthreads();
        uint32_t base = sb + (uint32_t)(kt & 1) * CSTG * 2;
        uint32_t a_hi = base, a_lo = base + MSTG * 2;
        uint32_t x_hi = base + 2 * MSTG * 2, x_lo = x_hi + XSTG * 2;

#pragma unroll
        for (int kk = 0; kk < CBK / 16; kk++) {
            uint32_t ah[4][4], al[4][4], bh[2][4], bl[2][4];
            int arow = m0 + (lane & 15);
            int acol = kk * 16 + (lane >> 4) * 8;
#pragma unroll
            for (int mi = 0; mi < 4; mi++) {
                uint32_t off = (uint32_t)((arow + mi * 16) * CLDM + acol) * 2;
                LDM_X4(ah[mi], a_hi + off);
                LDM_X4(al[mi], a_lo + off);
            }
            int krow = kk * 16 + ((lane >> 3) & 1) * 8 + (lane & 7);
            int ncol = (lane >> 4) * 8;
#pragma unroll
            for (int np = 0; np < 2; np++) {
                uint32_t off = (uint32_t)(krow * CLDX + n0w + np * 16 + ncol) * 2;
                LDM_X4T(bh[np], x_hi + off);
                LDM_X4T(bl[np], x_lo + off);
            }
#pragma unroll
            for (int mi = 0; mi < 4; mi++)
#pragma unroll
                for (int np = 0; np < 2; np++)
#pragma unroll
                    for (int h = 0; h < 2; h++) {
                        float* d = acc[mi][np * 2 + h];
                        MMA(d, ah[mi], bh[np][2 * h], bh[np][2 * h + 1]);
                        MMA(d, ah[mi], bl[np][2 * h], bl[np][2 * h + 1]);
                        MMA(d, al[mi], bh[np][2 * h], bh[np][2 * h + 1]);
                    }
        }
        __syncthreads();
        if (kt + 2 < NK) load_stage(kt & 1, (kt + 2) * CBK);
    }

    float* O = out + (size_t)b * N * L;
#pragma unroll
    for (int mi = 0; mi < 4; mi++) {
        int r0 = i0 + m0 + mi * 16 + (lane >> 2);
        float v0 = g_v[b][r0];
        float v1 = g_v[b][r0 + 8];
#pragma unroll
        for (int nj = 0; nj < 4; nj++) {
            float* d = acc[mi][nj];
            int c0 = l0 + n0w + nj * 8 + 2 * (lane & 3);
            *(float2*)&O[(size_t)r0 * L + c0] = make_float2(d[0] + v0, d[1] + v0);
            *(float2*)&O[(size_t)(r0 + 8) * L + c0] = make_float2(d[2] + v1, d[3] + v1);
        }
    }
}

// ---------------- launch ----------------
extern "C" void kernel_launch(void* const* d_in, const int* in_sizes, int n_in,
                              void* d_out, int out_size) {
    const float* xc = (const float*)d_in[0];
    const float* xs = (const float*)d_in[1];
    float* out = (float*)d_out;

    static int inited = 0;
    (void)inited;
    cudaFuncSetAttribute(k_gram_mma, cudaFuncAttributeMaxDynamicSharedMemorySize,
                         2 * 4 * GSTG * 2);
    cudaFuncSetAttribute(k_color_mma, cudaFuncAttributeMaxDynamicSharedMemorySize,
                         2 * CSTG * 2);

    k_convert<<<NMAT * N, 256>>>(xc, xs);
    k_gram_mma<<<384, 256, 2 * 4 * GSTG * 2>>>();
    k_reduce<<<NMAT * N, 256>>>();
    k_chol<<<NMAT, 256>>>();
    k_lct<<<B, 256>>>();
    k_solve<<<B * 8, 256>>>();
    k_convM<<<512, 256>>>();
    k_color_mma<<<B * 2 * 128, 256, 2 * CSTG * 2>>>(out);
}